// round 1
// baseline (speedup 1.0000x reference)
#include <cuda_runtime.h>
#include <stdint.h>
#include <math.h>

#define NB 2048
#define ND 256
#define NDT 768

// accumulators: [0]=mse sumsq, [1..7]=entropy row-sums S1,S2,S3,S13,S23,S12,S123
__device__ double g_acc[8];
__device__ unsigned int g_minbits[3];
__device__ float g_stats[NB * 18];   // per row, per k: mD, sD, tO, uD, mO, sO

__device__ __forceinline__ unsigned int fkey(float f) {
    unsigned int u = __float_as_uint(f);
    return (u & 0x80000000u) ? ~u : (u | 0x80000000u);
}
__device__ __forceinline__ float funkey(unsigned int u) {
    return __uint_as_float((u & 0x80000000u) ? (u & 0x7FFFFFFFu) : ~u);
}

__global__ void init_kernel() {
    int t = threadIdx.x;
    if (t < 8) g_acc[t] = 0.0;
    if (t < 3) g_minbits[t] = 0xFFFFFFFFu;
}

// ---------------- MSE: sum (data - output)^2 ----------------
__global__ void mse_kernel(const float* __restrict__ a, const float* __restrict__ b) {
    float s = 0.f;
    int stride = gridDim.x * blockDim.x;
    for (int i = blockIdx.x * blockDim.x + threadIdx.x; i < NB * NDT; i += stride) {
        float d = a[i] - b[i];
        s += d * d;
    }
    for (int o = 16; o; o >>= 1) s += __shfl_xor_sync(0xffffffffu, s, o);
    __shared__ float sm[32];
    int lane = threadIdx.x & 31, w = threadIdx.x >> 5;
    if (lane == 0) sm[w] = s;
    __syncthreads();
    if (threadIdx.x == 0) {
        double tot = 0.0;
        int nw = blockDim.x >> 5;
        for (int i = 0; i < nw; i++) tot += (double)sm[i];
        atomicAdd(&g_acc[0], tot);
    }
}

// ---------------- per-row softmax sufficient stats + global mins ----------------
// one warp per row; for each k in {1,2,3}:
//   mD=max(d), sD=sum e^{d-mD}, tO=sum e^{d-mD}*o, uD=sum e^{d-mD}*d, mO=max(o), sO=sum e^{o-mO}
__global__ void stats_kernel(const float* __restrict__ d1, const float* __restrict__ d2,
                             const float* __restrict__ d3,
                             const float* __restrict__ o1, const float* __restrict__ o2,
                             const float* __restrict__ o3) {
    int gw = (blockIdx.x * blockDim.x + threadIdx.x) >> 5;
    int lane = threadIdx.x & 31;
    if (gw >= NB) return;
    const float* ds[3] = {d1, d2, d3};
    const float* os[3] = {o1, o2, o3};
#pragma unroll
    for (int k = 0; k < 3; k++) {
        const float* dp = ds[k] + gw * ND;
        const float* op = os[k] + gw * ND;
        float vd[8], vo[8];
#pragma unroll
        for (int i = 0; i < 8; i++) { vd[i] = dp[lane + 32 * i]; vo[i] = op[lane + 32 * i]; }
        float mD = -INFINITY, mO = -INFINITY, mn = INFINITY;
#pragma unroll
        for (int i = 0; i < 8; i++) {
            mD = fmaxf(mD, vd[i]); mO = fmaxf(mO, vo[i]); mn = fminf(mn, vd[i]);
        }
        for (int o = 16; o; o >>= 1) {
            mD = fmaxf(mD, __shfl_xor_sync(0xffffffffu, mD, o));
            mO = fmaxf(mO, __shfl_xor_sync(0xffffffffu, mO, o));
            mn = fminf(mn, __shfl_xor_sync(0xffffffffu, mn, o));
        }
        float sD = 0.f, tO = 0.f, uD = 0.f, sO = 0.f;
#pragma unroll
        for (int i = 0; i < 8; i++) {
            float e = expf(vd[i] - mD);
            sD += e; tO += e * vo[i]; uD += e * vd[i];
            sO += expf(vo[i] - mO);
        }
        for (int o = 16; o; o >>= 1) {
            sD += __shfl_xor_sync(0xffffffffu, sD, o);
            tO += __shfl_xor_sync(0xffffffffu, tO, o);
            uD += __shfl_xor_sync(0xffffffffu, uD, o);
            sO += __shfl_xor_sync(0xffffffffu, sO, o);
        }
        if (lane == 0) {
            float* st = g_stats + gw * 18 + k * 6;
            st[0] = mD; st[1] = sD; st[2] = tO; st[3] = uD; st[4] = mO; st[5] = sO;
            atomicMin(&g_minbits[k], fkey(mn));
        }
    }
}

// ---------------- per-row joint entropies via packed pairwise equality ----------------
// labels: lab_k = floor((x - floor(min_k)) / 0.01), all < 2^16.
// pack lab1|lab2<<16 in one u32, lab3 in a second. All 7 subset equalities are
// XOR + mask tests. One block of 256 threads per row.
__global__ void entropy_kernel(const float* __restrict__ d1, const float* __restrict__ d2,
                               const float* __restrict__ d3) {
    __shared__ uint32_t s12[ND];
    __shared__ uint32_t s3a[ND];
    __shared__ float red[8 * 7];
    int row = blockIdx.x, t = threadIdx.x;
    float lo1 = floorf(funkey(g_minbits[0]));
    float lo2 = floorf(funkey(g_minbits[1]));
    float lo3 = floorf(funkey(g_minbits[2]));
    int idx = row * ND + t;
    uint32_t l1 = (uint32_t)(int)floorf(__fdiv_rn(d1[idx] - lo1, 0.01f));
    uint32_t l2 = (uint32_t)(int)floorf(__fdiv_rn(d2[idx] - lo2, 0.01f));
    uint32_t l3 = (uint32_t)(int)floorf(__fdiv_rn(d3[idx] - lo3, 0.01f));
    s12[t] = l1 | (l2 << 16);
    s3a[t] = l3;
    __syncthreads();
    uint32_t a = s12[t], b = s3a[t];
    int c1 = 0, c2 = 0, c3 = 0, c13 = 0, c23 = 0, c12 = 0, c123 = 0;
#pragma unroll 8
    for (int j = 0; j < ND; j++) {
        uint32_t xa = a ^ s12[j];
        uint32_t xb = b ^ s3a[j];
        int e1  = (xa & 0xFFFFu) == 0u;
        int e2  = (xa >> 16) == 0u;
        int e12 = (xa == 0u);
        int e3  = (xb == 0u);
        c1 += e1; c2 += e2; c3 += e3; c12 += e12;
        c13 += e1 & e3; c23 += e2 & e3; c123 += e12 & e3;
    }
    const float inv = 1.0f / 256.0f;
    float v[7] = { -logf((float)c1 * inv),  -logf((float)c2 * inv),  -logf((float)c3 * inv),
                   -logf((float)c13 * inv), -logf((float)c23 * inv), -logf((float)c12 * inv),
                   -logf((float)c123 * inv) };
    int lane = t & 31, w = t >> 5;
#pragma unroll
    for (int k = 0; k < 7; k++) {
        float x = v[k];
        for (int o = 16; o; o >>= 1) x += __shfl_xor_sync(0xffffffffu, x, o);
        if (lane == 0) red[w * 7 + k] = x;
    }
    __syncthreads();
    if (t == 0) {
        for (int k = 0; k < 7; k++) {
            double s = 0.0;
            for (int w2 = 0; w2 < 8; w2++) s += (double)red[w2 * 7 + k];
            atomicAdd(&g_acc[1 + k], s * (1.0 / 256.0));
        }
    }
}

// ---------------- final: reconstruct concat softmax terms, assemble scalar ----------------
__global__ void final_kernel(float* __restrict__ out) {
    __shared__ double red[256];
    const int masks[7] = {1, 2, 4, 5, 6, 3, 7}; // {1},{2},{3},{1,3},{2,3},{1,2},{1,2,3}
    double ceS[7] = {0, 0, 0, 0, 0, 0, 0}, klS[7] = {0, 0, 0, 0, 0, 0, 0};
    for (int row = threadIdx.x; row < NB; row += blockDim.x) {
        float st[18];
#pragma unroll
        for (int i = 0; i < 18; i++) st[i] = g_stats[row * 18 + i];
#pragma unroll
        for (int s = 0; s < 7; s++) {
            int m = masks[s];
            float M = -INFINITY, MO = -INFINITY;
#pragma unroll
            for (int k = 0; k < 3; k++)
                if (m & (1 << k)) { M = fmaxf(M, st[k * 6 + 0]); MO = fmaxf(MO, st[k * 6 + 4]); }
            float S = 0.f, T = 0.f, U = 0.f, SO = 0.f;
#pragma unroll
            for (int k = 0; k < 3; k++)
                if (m & (1 << k)) {
                    float w = expf(st[k * 6 + 0] - M);
                    S += st[k * 6 + 1] * w;
                    T += st[k * 6 + 2] * w;
                    U += st[k * 6 + 3] * w;
                    SO += st[k * 6 + 5] * expf(st[k * 6 + 4] - MO);
                }
            float lseD = M + logf(S);
            float lseO = MO + logf(SO);
            float Spo = T / S, Spd = U / S;
            // ce row = lseO - sum p*logq ; kl row-sum = sum p*(logp - logq)
            ceS[s] += (double)(lseO - Spo);
            klS[s] += (double)((Spd - lseD) - (Spo - lseO));
        }
    }
    double Hout[7];
    for (int s = 0; s < 7; s++) {
        red[threadIdx.x] = ceS[s]; __syncthreads();
        for (int off = 128; off; off >>= 1) {
            if (threadIdx.x < off) red[threadIdx.x] += red[threadIdx.x + off];
            __syncthreads();
        }
        double ce = red[0]; __syncthreads();
        red[threadIdx.x] = klS[s]; __syncthreads();
        for (int off = 128; off; off >>= 1) {
            if (threadIdx.x < off) red[threadIdx.x] += red[threadIdx.x + off];
            __syncthreads();
        }
        double kl = red[0]; __syncthreads();
        int C = ND * __popc(masks[s]);
        Hout[s] = ce / (double)NB - kl / ((double)NB * (double)C);
    }
    if (threadIdx.x == 0) {
        double Hd1 = g_acc[1] / NB, Hd2 = g_acc[2] / NB, Hd3 = g_acc[3] / NB;
        double Hin13 = g_acc[4] / NB, Hin23 = g_acc[5] / NB, Hin12 = g_acc[6] / NB;
        double H1 = Hd1 - Hout[0];
        double H2 = Hd2 - Hout[1];
        double H3 = Hd3 - Hout[2];
        double data13 = Hd1 + Hd3 - Hin13;
        double data23 = Hd2 + Hd3 - Hin23;
        double data12 = Hd1 + Hd2 - Hin12;
        double lab13 = Hout[0] + Hout[2] - Hout[3];
        double lab23 = Hout[1] + Hout[2] - Hout[4];
        double lab12 = Hout[0] + Hout[1] - Hout[5];
        double MI13 = lab13 - data13, MI23 = lab23 - data23, MI12 = lab12 - data12;
        // sum over rows (not mean): S13 + S23 - S3 - S123
        double aveDataCMI = g_acc[4] + g_acc[5] - g_acc[3] - g_acc[7];
        double aveLabCMI = Hout[4] - Hout[2] + Hout[3] - Hout[6];
        double CMI = aveLabCMI - aveDataCMI;
        double mse = 0.5 * (g_acc[0] / ((double)NB * (double)NDT));
        double loss = 0.5 * mse
                    + 0.25 * (H1 * H1 + H2 * H2 + H3 * H3)
                    + 0.25 * (MI13 * MI13 + MI23 * MI23 + MI12 * MI12 + CMI * CMI);
        out[0] = (float)loss;
    }
}

extern "C" void kernel_launch(void* const* d_in, const int* in_sizes, int n_in,
                              void* d_out, int out_size) {
    (void)in_sizes; (void)n_in; (void)out_size;
    const float* data  = (const float*)d_in[0];
    const float* data1 = (const float*)d_in[1];
    const float* data2 = (const float*)d_in[2];
    const float* data3 = (const float*)d_in[3];
    const float* out1  = (const float*)d_in[4];
    const float* out2  = (const float*)d_in[5];
    const float* out3  = (const float*)d_in[6];
    const float* outp  = (const float*)d_in[7];

    init_kernel<<<1, 32>>>();
    mse_kernel<<<512, 256>>>(data, outp);
    stats_kernel<<<NB / 8, 256>>>(data1, data2, data3, out1, out2, out3);
    entropy_kernel<<<NB, 256>>>(data1, data2, data3);
    final_kernel<<<1, 256>>>((float*)d_out);
}

// round 2
// speedup vs baseline: 3.7734x; 3.7734x over previous
#include <cuda_runtime.h>
#include <stdint.h>
#include <math.h>

#define NB 2048
#define ND 256
#define NDT 768
#define HS 512   // hash slots per subset (load factor <= 0.5)

// accumulators: [0]=mse sumsq, [1..7]=entropy row-sums S1,S2,S3,S13,S23,S12,S123
__device__ double g_acc[8];
__device__ double g_ck[14];          // ce,kl sums per 7 masks
__device__ unsigned int g_minbits[3];
__device__ float g_stats[NB * 18];   // per row, per k: mD, sD, tO, uD, mO, sO

__device__ __forceinline__ unsigned int fkey(float f) {
    unsigned int u = __float_as_uint(f);
    return (u & 0x80000000u) ? ~u : (u | 0x80000000u);
}
__device__ __forceinline__ float funkey(unsigned int u) {
    return __uint_as_float((u & 0x80000000u) ? (u & 0x7FFFFFFFu) : ~u);
}

__global__ void init_kernel() {
    int t = threadIdx.x;
    if (t < 8) g_acc[t] = 0.0;
    if (t < 14) g_ck[t] = 0.0;
    if (t < 3) g_minbits[t] = 0xFFFFFFFFu;
}

// ---------------- MSE: sum (data - output)^2 ----------------
__global__ void mse_kernel(const float* __restrict__ a, const float* __restrict__ b) {
    float s = 0.f;
    int stride = gridDim.x * blockDim.x;
    for (int i = blockIdx.x * blockDim.x + threadIdx.x; i < NB * NDT; i += stride) {
        float d = a[i] - b[i];
        s += d * d;
    }
    for (int o = 16; o; o >>= 1) s += __shfl_xor_sync(0xffffffffu, s, o);
    __shared__ float sm[32];
    int lane = threadIdx.x & 31, w = threadIdx.x >> 5;
    if (lane == 0) sm[w] = s;
    __syncthreads();
    if (threadIdx.x == 0) {
        double tot = 0.0;
        int nw = blockDim.x >> 5;
        for (int i = 0; i < nw; i++) tot += (double)sm[i];
        atomicAdd(&g_acc[0], tot);
    }
}

// ---------------- per-row softmax sufficient stats + global mins ----------------
__global__ void stats_kernel(const float* __restrict__ d1, const float* __restrict__ d2,
                             const float* __restrict__ d3,
                             const float* __restrict__ o1, const float* __restrict__ o2,
                             const float* __restrict__ o3) {
    int gw = (blockIdx.x * blockDim.x + threadIdx.x) >> 5;
    int lane = threadIdx.x & 31;
    if (gw >= NB) return;
    const float* ds[3] = {d1, d2, d3};
    const float* os[3] = {o1, o2, o3};
#pragma unroll
    for (int k = 0; k < 3; k++) {
        const float* dp = ds[k] + gw * ND;
        const float* op = os[k] + gw * ND;
        float vd[8], vo[8];
#pragma unroll
        for (int i = 0; i < 8; i++) { vd[i] = dp[lane + 32 * i]; vo[i] = op[lane + 32 * i]; }
        float mD = -INFINITY, mO = -INFINITY, mn = INFINITY;
#pragma unroll
        for (int i = 0; i < 8; i++) {
            mD = fmaxf(mD, vd[i]); mO = fmaxf(mO, vo[i]); mn = fminf(mn, vd[i]);
        }
        for (int o = 16; o; o >>= 1) {
            mD = fmaxf(mD, __shfl_xor_sync(0xffffffffu, mD, o));
            mO = fmaxf(mO, __shfl_xor_sync(0xffffffffu, mO, o));
            mn = fminf(mn, __shfl_xor_sync(0xffffffffu, mn, o));
        }
        float sD = 0.f, tO = 0.f, uD = 0.f, sO = 0.f;
#pragma unroll
        for (int i = 0; i < 8; i++) {
            float e = expf(vd[i] - mD);
            sD += e; tO += e * vo[i]; uD += e * vd[i];
            sO += expf(vo[i] - mO);
        }
        for (int o = 16; o; o >>= 1) {
            sD += __shfl_xor_sync(0xffffffffu, sD, o);
            tO += __shfl_xor_sync(0xffffffffu, tO, o);
            uD += __shfl_xor_sync(0xffffffffu, uD, o);
            sO += __shfl_xor_sync(0xffffffffu, sO, o);
        }
        if (lane == 0) {
            float* st = g_stats + gw * 18 + k * 6;
            st[0] = mD; st[1] = sD; st[2] = tO; st[3] = uD; st[4] = mO; st[5] = sO;
            atomicMin(&g_minbits[k], fkey(mn));
        }
    }
}

// ---------------- per-row joint entropies via shared-memory hash counting ----------------
// O(n) per subset instead of O(n^2) pairwise equality.
// Singles first: the claimed slot index (<512, 9 bits) is an injective per-row
// remap of the raw bin label, so pair keys (18b) and the triple key (27b) fit u32.
__global__ void entropy_kernel(const float* __restrict__ d1, const float* __restrict__ d2,
                               const float* __restrict__ d3) {
    __shared__ uint32_t hkey[HS];
    __shared__ uint32_t hcnt[HS];
    __shared__ float red[8 * 7];
    int row = blockIdx.x, t = threadIdx.x;
    float lo1 = floorf(funkey(g_minbits[0]));
    float lo2 = floorf(funkey(g_minbits[1]));
    float lo3 = floorf(funkey(g_minbits[2]));
    int idx = row * ND + t;
    uint32_t lab0 = (uint32_t)(int)floorf(__fdiv_rn(d1[idx] - lo1, 0.01f));
    uint32_t lab1 = (uint32_t)(int)floorf(__fdiv_rn(d2[idx] - lo2, 0.01f));
    uint32_t lab2 = (uint32_t)(int)floorf(__fdiv_rn(d3[idx] - lo3, 0.01f));

    uint32_t slot0 = 0, slot1 = 0, slot2 = 0;
    float lg[7];

#pragma unroll
    for (int s = 0; s < 7; s++) {
        uint32_t key;
        if (s == 0) key = lab0;
        else if (s == 1) key = lab1;
        else if (s == 2) key = lab2;
        else if (s == 3) key = slot0 | (slot2 << 9);
        else if (s == 4) key = slot1 | (slot2 << 9);
        else if (s == 5) key = slot0 | (slot1 << 9);
        else             key = slot0 | (slot1 << 9) | (slot2 << 18);

        // zero table
        hkey[t] = 0xFFFFFFFFu; hkey[t + 256] = 0xFFFFFFFFu;
        hcnt[t] = 0u;          hcnt[t + 256] = 0u;
        __syncthreads();

        uint32_t h = (key * 2654435769u) >> 23;  // 9-bit hash
        for (;;) {
            uint32_t old = atomicCAS(&hkey[h], 0xFFFFFFFFu, key);
            if (old == 0xFFFFFFFFu || old == key) break;
            h = (h + 1) & (HS - 1);
        }
        atomicAdd(&hcnt[h], 1u);
        if (s == 0) slot0 = h;
        else if (s == 1) slot1 = h;
        else if (s == 2) slot2 = h;
        __syncthreads();
        lg[s] = logf((float)hcnt[h] * (1.0f / 256.0f));
        __syncthreads();  // protect table before next zeroing
    }

    int lane = t & 31, w = t >> 5;
#pragma unroll
    for (int k = 0; k < 7; k++) {
        float x = lg[k];
        for (int o = 16; o; o >>= 1) x += __shfl_xor_sync(0xffffffffu, x, o);
        if (lane == 0) red[w * 7 + k] = x;
    }
    __syncthreads();
    if (t < 7) {
        double ssum = 0.0;
        for (int w2 = 0; w2 < 8; w2++) ssum += (double)red[w2 * 7 + t];
        atomicAdd(&g_acc[1 + t], -ssum * (1.0 / 256.0));
    }
}

// ---------------- grid-wide per-row softmax-entropy (ce/kl) accumulation ----------------
__global__ void hsoft_kernel() {
    const int masks[7] = {1, 2, 4, 5, 6, 3, 7}; // {1},{2},{3},{1,3},{2,3},{1,2},{1,2,3}
    int row = blockIdx.x * blockDim.x + threadIdx.x;
    float ce[7], kl[7];
    if (row < NB) {
        float st[18];
#pragma unroll
        for (int i = 0; i < 18; i++) st[i] = g_stats[row * 18 + i];
#pragma unroll
        for (int s = 0; s < 7; s++) {
            int m = masks[s];
            float M = -INFINITY, MO = -INFINITY;
#pragma unroll
            for (int k = 0; k < 3; k++)
                if (m & (1 << k)) { M = fmaxf(M, st[k * 6 + 0]); MO = fmaxf(MO, st[k * 6 + 4]); }
            float S = 0.f, T = 0.f, U = 0.f, SO = 0.f;
#pragma unroll
            for (int k = 0; k < 3; k++)
                if (m & (1 << k)) {
                    float w = expf(st[k * 6 + 0] - M);
                    S += st[k * 6 + 1] * w;
                    T += st[k * 6 + 2] * w;
                    U += st[k * 6 + 3] * w;
                    SO += st[k * 6 + 5] * expf(st[k * 6 + 4] - MO);
                }
            float lseD = M + logf(S);
            float lseO = MO + logf(SO);
            float Spo = T / S, Spd = U / S;
            ce[s] = lseO - Spo;
            kl[s] = (Spd - lseD) - (Spo - lseO);
        }
    } else {
#pragma unroll
        for (int s = 0; s < 7; s++) { ce[s] = 0.f; kl[s] = 0.f; }
    }
    int lane = threadIdx.x & 31;
#pragma unroll
    for (int s = 0; s < 7; s++) {
        float c = ce[s], k = kl[s];
        for (int o = 16; o; o >>= 1) {
            c += __shfl_xor_sync(0xffffffffu, c, o);
            k += __shfl_xor_sync(0xffffffffu, k, o);
        }
        if (lane == 0) {
            atomicAdd(&g_ck[s], (double)c);
            atomicAdd(&g_ck[7 + s], (double)k);
        }
    }
}

// ---------------- finish: assemble scalar ----------------
__global__ void finish_kernel(float* __restrict__ out) {
    const int masks[7] = {1, 2, 4, 5, 6, 3, 7};
    double Hout[7];
    for (int s = 0; s < 7; s++) {
        int C = ND * __popc(masks[s]);
        Hout[s] = g_ck[s] / (double)NB - g_ck[7 + s] / ((double)NB * (double)C);
    }
    double Hd1 = g_acc[1] / NB, Hd2 = g_acc[2] / NB, Hd3 = g_acc[3] / NB;
    double Hin13 = g_acc[4] / NB, Hin23 = g_acc[5] / NB, Hin12 = g_acc[6] / NB;
    double H1 = Hd1 - Hout[0];
    double H2 = Hd2 - Hout[1];
    double H3 = Hd3 - Hout[2];
    double data13 = Hd1 + Hd3 - Hin13;
    double data23 = Hd2 + Hd3 - Hin23;
    double data12 = Hd1 + Hd2 - Hin12;
    double lab13 = Hout[0] + Hout[2] - Hout[3];
    double lab23 = Hout[1] + Hout[2] - Hout[4];
    double lab12 = Hout[0] + Hout[1] - Hout[5];
    double MI13 = lab13 - data13, MI23 = lab23 - data23, MI12 = lab12 - data12;
    // per-row CMI summed over rows: S13 + S23 - S3 - S123
    double aveDataCMI = g_acc[4] + g_acc[5] - g_acc[3] - g_acc[7];
    double aveLabCMI = Hout[4] - Hout[2] + Hout[3] - Hout[6];
    double CMI = aveLabCMI - aveDataCMI;
    double mse = 0.5 * (g_acc[0] / ((double)NB * (double)NDT));
    double loss = 0.5 * mse
                + 0.25 * (H1 * H1 + H2 * H2 + H3 * H3)
                + 0.25 * (MI13 * MI13 + MI23 * MI23 + MI12 * MI12 + CMI * CMI);
    out[0] = (float)loss;
}

extern "C" void kernel_launch(void* const* d_in, const int* in_sizes, int n_in,
                              void* d_out, int out_size) {
    (void)in_sizes; (void)n_in; (void)out_size;
    const float* data  = (const float*)d_in[0];
    const float* data1 = (const float*)d_in[1];
    const float* data2 = (const float*)d_in[2];
    const float* data3 = (const float*)d_in[3];
    const float* out1  = (const float*)d_in[4];
    const float* out2  = (const float*)d_in[5];
    const float* out3  = (const float*)d_in[6];
    const float* outp  = (const float*)d_in[7];

    init_kernel<<<1, 32>>>();
    mse_kernel<<<512, 256>>>(data, outp);
    stats_kernel<<<NB / 8, 256>>>(data1, data2, data3, out1, out2, out3);
    entropy_kernel<<<NB, 256>>>(data1, data2, data3);
    hsoft_kernel<<<NB / 256, 256>>>();
    finish_kernel<<<1, 1>>>((float*)d_out);
}